// round 1
// baseline (speedup 1.0000x reference)
#include <cuda_runtime.h>
#include <math.h>

// ---------------- geometry ----------------
#define IMG_W   512
#define IMG_H   512
#define NCH     96            // 32 batch * 3 channels
#define OX      64            // output tile width per block
#define OY      32            // output tile height per block
#define INX     74            // OX + 10 halo
#define SX      76            // padded smem row stride for inputs (16B aligned)
#define INY     42            // OY + 10 halo
#define HX      65            // hbuf row stride (odd -> conflict-free vertical reads)
#define HROW    (INY*HX)      // 2730 floats per field
#define GRID_X  (IMG_W/OX)    // 8
#define GRID_Y  (IMG_H/OY)    // 16
#define NBLK    (GRID_X*GRID_Y*NCH)   // 12288
#define NTHREADS 256
#define C2      0.0009f
#define NPIX    25165824.0f   // 32*3*512*512

#define SMEM_FLOATS (2*INY*SX + 5*HROW)     // 6384 + 13650 = 20034
#define SMEM_BYTES  (SMEM_FLOATS * 4)       // 80136

__device__ float g_blocksums[NBLK];

extern __shared__ float sm[];

__global__ void __launch_bounds__(NTHREADS, 2)
ssim_kernel(const float* __restrict__ img1, const float* __restrict__ img2)
{
    // Gaussian weights (sigma=1.5, window=11, normalized). Local const array +
    // fully unrolled loops -> ptxas folds these to FFMA immediates.
    const float G[11] = {
        0.00102838f, 0.00759878f, 0.03600068f, 0.10936072f, 0.21300538f,
        0.26601175f, 0.21300538f, 0.10936072f, 0.03600068f, 0.00759878f,
        0.00102838f };

    float* s1m = sm;                 // [INY][SX]
    float* s2m = sm + INY*SX;        // [INY][SX]
    float* sh  = sm + 2*INY*SX;      // [5][INY][HX]

    const int tid = threadIdx.x;
    const int tx0 = blockIdx.x * OX;
    const int ty0 = blockIdx.y * OY;
    const int ch  = blockIdx.z;
    const float* p1 = img1 + (size_t)ch * (IMG_W*IMG_H);
    const float* p2 = img2 + (size_t)ch * (IMG_W*IMG_H);

    // ---------- phase 0: cooperative load with zero padding ----------
    for (int idx = tid; idx < INY*SX; idx += NTHREADS) {
        int row = idx / SX;
        int col = idx - row * SX;
        float v1 = 0.f, v2 = 0.f;
        int gx = tx0 - 5 + col;
        int gy = ty0 - 5 + row;
        if (col < INX && gx >= 0 && gx < IMG_W && gy >= 0 && gy < IMG_H) {
            int gi = gy * IMG_W + gx;
            v1 = __ldg(p1 + gi);
            v2 = __ldg(p2 + gi);
        }
        s1m[idx] = v1;
        s2m[idx] = v2;
    }
    __syncthreads();

    // ---------- phase 1: horizontal 11-tap, 5 fields ----------
    // thread -> (row group, column group of 4 outputs)
    {
        const int cg = tid & 15;         // column group: outputs [4cg, 4cg+3]
        const int r0 = tid >> 4;         // row 0..15; covers rows r0, r0+16, r0+32
        #pragma unroll
        for (int rr = 0; rr < 3; rr++) {
            const int r = r0 + rr * 16;
            if (r < INY) {
                const float4* pa = (const float4*)(s1m + r*SX + cg*4);
                const float4* pb = (const float4*)(s2m + r*SX + cg*4);
                float a[16], b[16];
                #pragma unroll
                for (int q = 0; q < 4; q++) {
                    float4 va = pa[q], vb = pb[q];
                    a[4*q+0] = va.x; a[4*q+1] = va.y; a[4*q+2] = va.z; a[4*q+3] = va.w;
                    b[4*q+0] = vb.x; b[4*q+1] = vb.y; b[4*q+2] = vb.z; b[4*q+3] = vb.w;
                }
                float acc[5][4];
                #pragma unroll
                for (int f = 0; f < 5; f++)
                    #pragma unroll
                    for (int c = 0; c < 4; c++) acc[f][c] = 0.f;

                // per loaded value: products once, then immediate-weight FMAs
                #pragma unroll
                for (int v = 0; v < 14; v++) {
                    const float av = a[v], bv = b[v];
                    const float aa = av*av, bb = bv*bv, ab = av*bv;
                    #pragma unroll
                    for (int c = 0; c < 4; c++) {
                        const int k = v - c;
                        if (k >= 0 && k < 11) {
                            acc[0][c] += G[k] * av;
                            acc[1][c] += G[k] * bv;
                            acc[2][c] += G[k] * aa;
                            acc[3][c] += G[k] * bb;
                            acc[4][c] += G[k] * ab;
                        }
                    }
                }
                const int base = r*HX + cg*4;
                #pragma unroll
                for (int f = 0; f < 5; f++)
                    #pragma unroll
                    for (int c = 0; c < 4; c++)
                        sh[f*HROW + base + c] = acc[f][c];
            }
        }
    }
    __syncthreads();

    // ---------- phase 2: vertical 11-tap + SSIM epilogue ----------
    float tsum = 0.f;
    {
        const int x  = tid & 63;
        const int yb = (tid >> 6) * 8;       // 8 output rows per thread
        float acc[5][8];
        #pragma unroll
        for (int f = 0; f < 5; f++)
            #pragma unroll
            for (int r = 0; r < 8; r++) acc[f][r] = 0.f;

        #pragma unroll
        for (int j = 0; j < 18; j++) {
            const int yy = yb + j;
            const float v0 = sh[0*HROW + yy*HX + x];
            const float v1 = sh[1*HROW + yy*HX + x];
            const float v2 = sh[2*HROW + yy*HX + x];
            const float v3 = sh[3*HROW + yy*HX + x];
            const float v4 = sh[4*HROW + yy*HX + x];
            #pragma unroll
            for (int r = 0; r < 8; r++) {
                const int k = j - r;
                if (k >= 0 && k < 11) {
                    acc[0][r] += G[k] * v0;
                    acc[1][r] += G[k] * v1;
                    acc[2][r] += G[k] * v2;
                    acc[3][r] += G[k] * v3;
                    acc[4][r] += G[k] * v4;
                }
            }
        }

        #pragma unroll
        for (int r = 0; r < 8; r++) {
            const float mu1 = acc[0][r], mu2 = acc[1][r];
            const float s11 = acc[2][r] - mu1*mu1;
            const float s22 = acc[3][r] - mu2*mu2;
            const float s12 = acc[4][r] - mu1*mu2;
            const float num = s12 + C2;
            const float den = sqrtf(fabsf(s11) * fabsf(s22)) + C2;
            tsum += num / den;
        }
    }

    // ---------- block reduction (deterministic within block) ----------
    #pragma unroll
    for (int o = 16; o; o >>= 1) tsum += __shfl_down_sync(0xFFFFFFFFu, tsum, o);
    __shared__ float wsum[8];
    if ((tid & 31) == 0) wsum[tid >> 5] = tsum;
    __syncthreads();
    if (tid == 0) {
        float s = 0.f;
        #pragma unroll
        for (int i = 0; i < 8; i++) s += wsum[i];
        g_blocksums[(blockIdx.z * GRID_Y + blockIdx.y) * GRID_X + blockIdx.x] = s;
    }
}

__global__ void __launch_bounds__(1024, 1)
reduce_kernel(float* __restrict__ out)
{
    const int tid = threadIdx.x;
    float s = 0.f;
    for (int i = tid; i < NBLK; i += 1024) s += g_blocksums[i];
    #pragma unroll
    for (int o = 16; o; o >>= 1) s += __shfl_down_sync(0xFFFFFFFFu, s, o);
    __shared__ float ws[32];
    if ((tid & 31) == 0) ws[tid >> 5] = s;
    __syncthreads();
    if (tid < 32) {
        float v = ws[tid];
        #pragma unroll
        for (int o = 16; o; o >>= 1) v += __shfl_down_sync(0xFFFFFFFFu, v, o);
        if (tid == 0) out[0] = v / NPIX;
    }
}

extern "C" void kernel_launch(void* const* d_in, const int* in_sizes, int n_in,
                              void* d_out, int out_size)
{
    const float* img1 = (const float*)d_in[0];
    const float* img2 = (const float*)d_in[1];
    float* out = (float*)d_out;

    cudaFuncSetAttribute(ssim_kernel,
                         cudaFuncAttributeMaxDynamicSharedMemorySize, SMEM_BYTES);

    dim3 grid(GRID_X, GRID_Y, NCH);
    ssim_kernel<<<grid, NTHREADS, SMEM_BYTES>>>(img1, img2);
    reduce_kernel<<<1, 1024>>>(out);
}

// round 2
// speedup vs baseline: 1.4095x; 1.4095x over previous
#include <cuda_runtime.h>
#include <math.h>

// ---------------- geometry ----------------
#define IMG_W   512
#define IMG_H   512
#define NCH     96            // 32 batch * 3 channels
#define OX      64            // output tile width per block
#define OY      32            // output tile height per block
#define INX     74            // OX + 10 halo
#define SX      76            // padded smem row stride for inputs (16B-aligned float4 loads)
#define INY     42            // OY + 10 halo
#define HX2     66            // hbuf row stride in float2/ull elements (mu-pair, sq-pair)
#define HXX     68            // hbuf row stride in floats for cross field (272B -> 16B aligned rows)
#define GRID_X  (IMG_W/OX)    // 8
#define GRID_Y  (IMG_H/OY)    // 16
#define NBLK    (GRID_X*GRID_Y*NCH)   // 12288
#define NTHREADS 512
#define C2      0.0009f
#define NPIX    25165824.0f   // 32*3*512*512

// smem layout (float offsets)
#define OFF_S1  0
#define OFF_S2  (INY*SX)                  // 3192
#define OFF_M   (2*INY*SX)                // 6384   : ull [INY][HX2]  (mu1,mu2)
#define OFF_S   (OFF_M + 2*INY*HX2)       // 11928  : ull [INY][HX2]  (E[x2],E[y2])
#define OFF_X   (OFF_S + 2*INY*HX2)       // 17472  : f32 [INY][HXX]  (E[xy])
#define SMEM_FLOATS (OFF_X + INY*HXX)     // 20328
#define SMEM_BYTES  (SMEM_FLOATS * 4)     // 81312

typedef unsigned long long ull;

__device__ float g_blocksums[NBLK];

// Gaussian weights (sigma=1.5, window=11, normalized), symmetric.
__device__ __forceinline__ float Gw(int k) {
    constexpr float g[11] = {
        0.00102838f, 0.00759878f, 0.03600068f, 0.10936072f, 0.21300538f,
        0.26601175f, 0.21300538f, 0.10936072f, 0.03600068f, 0.00759878f,
        0.00102838f };
    return g[k];
}

// -------- f32x2 packed helpers (FFMA2 path, PTX-only) --------
__device__ __forceinline__ ull dup2(float g) {
    return ((ull)__float_as_uint(g) << 32) | (ull)__float_as_uint(g);
}
__device__ __forceinline__ ull pk2(float lo, float hi) {
    ull r; asm("mov.b64 %0, {%1, %2};" : "=l"(r) : "f"(lo), "f"(hi)); return r;
}
__device__ __forceinline__ ull fma2(ull a, ull b, ull c) {
    ull d; asm("fma.rn.f32x2 %0, %1, %2, %3;" : "=l"(d) : "l"(a), "l"(b), "l"(c)); return d;
}
__device__ __forceinline__ ull mul2(ull a, ull b) {
    ull d; asm("mul.rn.f32x2 %0, %1, %2;" : "=l"(d) : "l"(a), "l"(b)); return d;
}
__device__ __forceinline__ float lo2(ull v) {
    float f; asm("{ .reg .b32 h; mov.b64 {%0, h}, %1; }" : "=f"(f) : "l"(v)); return f;
}
__device__ __forceinline__ float hi2(ull v) {
    float f; asm("{ .reg .b32 l; mov.b64 {l, %0}, %1; }" : "=f"(f) : "l"(v)); return f;
}

extern __shared__ float sm[];

__global__ void __launch_bounds__(NTHREADS, 2)
ssim_kernel(const float* __restrict__ img1, const float* __restrict__ img2)
{
    float* s1m = sm + OFF_S1;
    float* s2m = sm + OFF_S2;
    ull*   hM  = (ull*)(sm + OFF_M);     // [INY][HX2]
    ull*   hS  = (ull*)(sm + OFF_S);     // [INY][HX2]
    float* hX  = sm + OFF_X;             // [INY][HXX]

    const int tid = threadIdx.x;
    const int tx0 = blockIdx.x * OX;
    const int ty0 = blockIdx.y * OY;
    const int ch  = blockIdx.z;
    const float* p1 = img1 + (size_t)ch * (IMG_W*IMG_H);
    const float* p2 = img2 + (size_t)ch * (IMG_W*IMG_H);

    // ---------- phase 0: cooperative load with zero padding ----------
    for (int idx = tid; idx < INY*SX; idx += NTHREADS) {
        int row = idx / SX;
        int col = idx - row * SX;
        float v1 = 0.f, v2 = 0.f;
        int gx = tx0 - 5 + col;
        int gy = ty0 - 5 + row;
        if (col < INX && gx >= 0 && gx < IMG_W && gy >= 0 && gy < IMG_H) {
            int gi = gy * IMG_W + gx;
            v1 = __ldg(p1 + gi);
            v2 = __ldg(p2 + gi);
        }
        s1m[idx] = v1;
        s2m[idx] = v2;
    }
    __syncthreads();

    // ---------- phase 1: horizontal 11-tap, packed fields ----------
    // thread -> (row, column group of 4 outputs). 16 cg x 32 rows per pass, 2 passes.
    {
        const int cg = tid & 15;         // outputs [4cg, 4cg+3]
        const int r0 = tid >> 4;         // 0..31
        #pragma unroll
        for (int rr = 0; rr < 2; rr++) {
            const int r = r0 + rr * 32;
            if (r < INY) {
                const float* s1 = s1m + r*SX + cg*4;
                const float* s2 = s2m + r*SX + cg*4;
                ull accM[4] = {0ull,0ull,0ull,0ull};
                ull accS[4] = {0ull,0ull,0ull,0ull};
                float accX[4] = {0.f,0.f,0.f,0.f};

                #pragma unroll
                for (int q = 0; q < 4; q++) {
                    const float4 va = *(const float4*)(s1 + q*4);
                    const float4 vb = *(const float4*)(s2 + q*4);
                    const float av[4] = {va.x, va.y, va.z, va.w};
                    const float bv[4] = {vb.x, vb.y, vb.z, vb.w};
                    #pragma unroll
                    for (int s = 0; s < 4; s++) {
                        const int v = q*4 + s;
                        if (v < 14) {
                            const float a = av[s], b = bv[s];
                            const ull mp = pk2(a, b);
                            const ull sp = mul2(mp, mp);
                            const float ab = a * b;
                            #pragma unroll
                            for (int c = 0; c < 4; c++) {
                                const int k = v - c;
                                if (k >= 0 && k < 11) {
                                    const ull gg = dup2(Gw(k));
                                    accM[c] = fma2(mp, gg, accM[c]);
                                    accS[c] = fma2(sp, gg, accS[c]);
                                    accX[c] = fmaf(Gw(k), ab, accX[c]);
                                }
                            }
                        }
                    }
                }
                // packed stores: 2x STS.128 per field + 1x STS.128 cross
                ulonglong2* dM = (ulonglong2*)(hM + r*HX2 + cg*4);
                ulonglong2* dS = (ulonglong2*)(hS + r*HX2 + cg*4);
                dM[0] = make_ulonglong2(accM[0], accM[1]);
                dM[1] = make_ulonglong2(accM[2], accM[3]);
                dS[0] = make_ulonglong2(accS[0], accS[1]);
                dS[1] = make_ulonglong2(accS[2], accS[3]);
                *(float4*)(hX + r*HXX + cg*4) =
                    make_float4(accX[0], accX[1], accX[2], accX[3]);
            }
        }
    }
    __syncthreads();

    // ---------- phase 2: vertical 11-tap + SSIM epilogue ----------
    float tsum = 0.f;
    {
        const int x  = tid & 63;
        const int yb = (tid >> 6) * 4;       // 4 output rows per thread
        ull accM[4] = {0ull,0ull,0ull,0ull};
        ull accS[4] = {0ull,0ull,0ull,0ull};
        float accX[4] = {0.f,0.f,0.f,0.f};

        #pragma unroll
        for (int j = 0; j < 14; j++) {
            const int yy = yb + j;
            const ull  vM = hM[yy*HX2 + x];
            const ull  vS = hS[yy*HX2 + x];
            const float vX = hX[yy*HXX + x];
            #pragma unroll
            for (int r = 0; r < 4; r++) {
                const int k = j - r;
                if (k >= 0 && k < 11) {
                    const ull gg = dup2(Gw(k));
                    accM[r] = fma2(vM, gg, accM[r]);
                    accS[r] = fma2(vS, gg, accS[r]);
                    accX[r] = fmaf(Gw(k), vX, accX[r]);
                }
            }
        }

        #pragma unroll
        for (int r = 0; r < 4; r++) {
            const float mu1 = lo2(accM[r]), mu2 = hi2(accM[r]);
            const float e11 = lo2(accS[r]), e22 = hi2(accS[r]);
            const float s11 = e11 - mu1*mu1;
            const float s22 = e22 - mu2*mu2;
            const float s12 = accX[r] - mu1*mu2;
            const float num = s12 + C2;
            const float den = sqrtf(fabsf(s11) * fabsf(s22)) + C2;
            tsum += __fdividef(num, den);
        }
    }

    // ---------- block reduction (deterministic within block) ----------
    #pragma unroll
    for (int o = 16; o; o >>= 1) tsum += __shfl_down_sync(0xFFFFFFFFu, tsum, o);
    __shared__ float wsum[16];
    if ((tid & 31) == 0) wsum[tid >> 5] = tsum;
    __syncthreads();
    if (tid == 0) {
        float s = 0.f;
        #pragma unroll
        for (int i = 0; i < 16; i++) s += wsum[i];
        g_blocksums[(blockIdx.z * GRID_Y + blockIdx.y) * GRID_X + blockIdx.x] = s;
    }
}

__global__ void __launch_bounds__(1024, 1)
reduce_kernel(float* __restrict__ out)
{
    const int tid = threadIdx.x;
    const float4* src = (const float4*)g_blocksums;
    float s = 0.f;
    #pragma unroll
    for (int i = 0; i < NBLK/4/1024; i++) {
        float4 v = src[tid + i * 1024];
        s += (v.x + v.y) + (v.z + v.w);
    }
    #pragma unroll
    for (int o = 16; o; o >>= 1) s += __shfl_down_sync(0xFFFFFFFFu, s, o);
    __shared__ float ws[32];
    if ((tid & 31) == 0) ws[tid >> 5] = s;
    __syncthreads();
    if (tid < 32) {
        float v = ws[tid];
        #pragma unroll
        for (int o = 16; o; o >>= 1) v += __shfl_down_sync(0xFFFFFFFFu, v, o);
        if (tid == 0) out[0] = v / NPIX;
    }
}

extern "C" void kernel_launch(void* const* d_in, const int* in_sizes, int n_in,
                              void* d_out, int out_size)
{
    const float* img1 = (const float*)d_in[0];
    const float* img2 = (const float*)d_in[1];
    float* out = (float*)d_out;

    cudaFuncSetAttribute(ssim_kernel,
                         cudaFuncAttributeMaxDynamicSharedMemorySize, SMEM_BYTES);

    dim3 grid(GRID_X, GRID_Y, NCH);
    ssim_kernel<<<grid, NTHREADS, SMEM_BYTES>>>(img1, img2);
    reduce_kernel<<<1, 1024>>>(out);
}

// round 3
// speedup vs baseline: 1.7276x; 1.2257x over previous
#include <cuda_runtime.h>
#include <math.h>

// ---------------- geometry ----------------
#define IMG_W   512
#define IMG_H   512
#define NCH     96            // 32 batch * 3 channels
#define OX      64            // output tile width per block
#define OY      32            // output tile height per block
#define INY     42            // OY + 10 halo rows of horizontal-pass output
#define HXM     66            // ulonglong2 (16B) stride per row: interleaved (M,S)
#define HXX     68            // float stride per row: cross field
#define GRID_X  (IMG_W/OX)    // 8
#define GRID_Y  (IMG_H/OY)    // 16
#define NBLK    (GRID_X*GRID_Y*NCH)   // 12288
#define NTHREADS 512
#define C2      0.0009f
#define NPIX    25165824.0f

#define SMEM_BYTES (INY*HXM*16 + INY*HXX*4)   // 44352 + 11424 = 55776

typedef unsigned long long ull;

__device__ float g_blocksums[NBLK];

// Gaussian weights (sigma=1.5, window=11, normalized), symmetric.
__device__ __forceinline__ constexpr float Gw(int k) {
    constexpr float g[11] = {
        0.00102838f, 0.00759878f, 0.03600068f, 0.10936072f, 0.21300538f,
        0.26601175f, 0.21300538f, 0.10936072f, 0.03600068f, 0.00759878f,
        0.00102838f };
    return g[k];
}

// -------- f32x2 packed helpers --------
__device__ __forceinline__ constexpr ull dup2c(float g) {
    return ((ull)__builtin_bit_cast(unsigned, g) << 32) |
           (ull)__builtin_bit_cast(unsigned, g);
}
__device__ __forceinline__ ull pk2(float lo, float hi) {
    ull r; asm("mov.b64 %0, {%1, %2};" : "=l"(r) : "f"(lo), "f"(hi)); return r;
}
__device__ __forceinline__ ull fma2(ull a, ull b, ull c) {
    ull d; asm("fma.rn.f32x2 %0, %1, %2, %3;" : "=l"(d) : "l"(a), "l"(b), "l"(c)); return d;
}
__device__ __forceinline__ ull mul2(ull a, ull b) {
    ull d; asm("mul.rn.f32x2 %0, %1, %2;" : "=l"(d) : "l"(a), "l"(b)); return d;
}
__device__ __forceinline__ float lo2(ull v) {
    float f; asm("{ .reg .b32 h; mov.b64 {%0, h}, %1; }" : "=f"(f) : "l"(v)); return f;
}
__device__ __forceinline__ float hi2(ull v) {
    float f; asm("{ .reg .b32 l; mov.b64 {l, %0}, %1; }" : "=f"(f) : "l"(v)); return f;
}
__device__ __forceinline__ float rsqrt_approx(float v) {
    float r; asm("rsqrt.approx.f32 %0, %1;" : "=f"(r) : "f"(v)); return r;
}
__device__ __forceinline__ float rcp_approx(float v) {
    float r; asm("rcp.approx.f32 %0, %1;" : "=f"(r) : "f"(v)); return r;
}

extern __shared__ float sm[];

// ---------- phase A task: horizontal 11-tap from gmem, 4 output cols ----------
template <bool FULLX>
__device__ __forceinline__ void phaseA_task(
    int t, int tx0, int ty0,
    const float* __restrict__ p1, const float* __restrict__ p2,
    ulonglong2* __restrict__ hMS, float* __restrict__ hX)
{
    const int cg = t & 15;
    const int r  = t >> 4;                 // 0..41
    const int gy = ty0 - 5 + r;

    ull accM[4] = {0ull,0ull,0ull,0ull};
    ull accS[4] = {0ull,0ull,0ull,0ull};
    float accX[4] = {0.f,0.f,0.f,0.f};

    if (gy >= 0 && gy < IMG_H) {
        const int gxb = tx0 + cg*4 - 5;
        const float* q1 = p1 + gy*IMG_W + gxb;
        const float* q2 = p2 + gy*IMG_W + gxb;
        #pragma unroll
        for (int v = 0; v < 14; v++) {
            float a, b;
            if (FULLX) {
                a = __ldg(q1 + v);
                b = __ldg(q2 + v);
            } else {
                const int gx = gxb + v;
                const bool ok = (gx >= 0) && (gx < IMG_W);
                a = ok ? __ldg(q1 + v) : 0.f;
                b = ok ? __ldg(q2 + v) : 0.f;
            }
            const ull mp = pk2(a, b);
            const ull sp = mul2(mp, mp);
            const float ab = a * b;
            #pragma unroll
            for (int c = 0; c < 4; c++) {
                const int k = v - c;
                if (k >= 0 && k < 11) {
                    const ull gg = dup2c(Gw(k));
                    accM[c] = fma2(mp, gg, accM[c]);
                    accS[c] = fma2(sp, gg, accS[c]);
                    accX[c] = fmaf(Gw(k), ab, accX[c]);
                }
            }
        }
    }
    // store (also zero rows): interleaved (M,S) per column + cross float4
    const int base = r*HXM + cg*4;
    #pragma unroll
    for (int c = 0; c < 4; c++)
        hMS[base + c] = make_ulonglong2(accM[c], accS[c]);
    *(float4*)(hX + r*HXX + cg*4) = make_float4(accX[0], accX[1], accX[2], accX[3]);
}

__global__ void __launch_bounds__(NTHREADS, 3)
ssim_kernel(const float* __restrict__ img1, const float* __restrict__ img2)
{
    ulonglong2* hMS = (ulonglong2*)sm;               // [INY][HXM]
    float*      hX  = sm + (INY*HXM*16)/4;           // [INY][HXX]

    const int tid = threadIdx.x;
    const int tx0 = blockIdx.x * OX;
    const int ty0 = blockIdx.y * OY;
    const int ch  = blockIdx.z;
    const float* p1 = img1 + (size_t)ch * (IMG_W*IMG_H);
    const float* p2 = img2 + (size_t)ch * (IMG_W*IMG_H);

    // ---------- phase A: horizontal pass, gmem -> smem hbuf ----------
    const bool fullx = (blockIdx.x != 0) && (blockIdx.x != GRID_X-1);
    if (fullx) {
        phaseA_task<true>(tid, tx0, ty0, p1, p2, hMS, hX);
        if (tid < INY*16 - NTHREADS)
            phaseA_task<true>(tid + NTHREADS, tx0, ty0, p1, p2, hMS, hX);
    } else {
        phaseA_task<false>(tid, tx0, ty0, p1, p2, hMS, hX);
        if (tid < INY*16 - NTHREADS)
            phaseA_task<false>(tid + NTHREADS, tx0, ty0, p1, p2, hMS, hX);
    }
    __syncthreads();

    // ---------- phase B: vertical 11-tap + SSIM epilogue ----------
    float tsum = 0.f;
    {
        const int x  = tid & 63;
        const int yb = (tid >> 6) * 4;       // 4 output rows per thread
        ull accM[4] = {0ull,0ull,0ull,0ull};
        ull accS[4] = {0ull,0ull,0ull,0ull};
        float accX[4] = {0.f,0.f,0.f,0.f};

        #pragma unroll
        for (int j = 0; j < 14; j++) {
            const int yy = yb + j;
            const ulonglong2 ms = hMS[yy*HXM + x];
            const float vX = hX[yy*HXX + x];
            #pragma unroll
            for (int r = 0; r < 4; r++) {
                const int k = j - r;
                if (k >= 0 && k < 11) {
                    const ull gg = dup2c(Gw(k));
                    accM[r] = fma2(ms.x, gg, accM[r]);
                    accS[r] = fma2(ms.y, gg, accS[r]);
                    accX[r] = fmaf(Gw(k), vX, accX[r]);
                }
            }
        }

        #pragma unroll
        for (int r = 0; r < 4; r++) {
            const float mu1 = lo2(accM[r]), mu2 = hi2(accM[r]);
            const float e11 = lo2(accS[r]), e22 = hi2(accS[r]);
            const float s11 = e11 - mu1*mu1;
            const float s22 = e22 - mu2*mu2;
            const float s12 = accX[r] - mu1*mu2;
            const float num = s12 + C2;
            float v = fabsf(s11) * fabsf(s22);
            v = fmaxf(v, 1e-30f);
            const float den = fmaf(v, rsqrt_approx(v), C2);  // sqrt(v) + C2
            tsum = fmaf(num, rcp_approx(den), tsum);
        }
    }

    // ---------- block reduction (deterministic within block) ----------
    #pragma unroll
    for (int o = 16; o; o >>= 1) tsum += __shfl_down_sync(0xFFFFFFFFu, tsum, o);
    __shared__ float wsum[16];
    if ((tid & 31) == 0) wsum[tid >> 5] = tsum;
    __syncthreads();
    if (tid == 0) {
        float s = 0.f;
        #pragma unroll
        for (int i = 0; i < 16; i++) s += wsum[i];
        g_blocksums[(blockIdx.z * GRID_Y + blockIdx.y) * GRID_X + blockIdx.x] = s;
    }
}

__global__ void __launch_bounds__(1024, 1)
reduce_kernel(float* __restrict__ out)
{
    const int tid = threadIdx.x;
    const float4* src = (const float4*)g_blocksums;
    float s = 0.f;
    #pragma unroll
    for (int i = 0; i < NBLK/4/1024; i++) {
        float4 v = src[tid + i * 1024];
        s += (v.x + v.y) + (v.z + v.w);
    }
    #pragma unroll
    for (int o = 16; o; o >>= 1) s += __shfl_down_sync(0xFFFFFFFFu, s, o);
    __shared__ float ws[32];
    if ((tid & 31) == 0) ws[tid >> 5] = s;
    __syncthreads();
    if (tid < 32) {
        float v = ws[tid];
        #pragma unroll
        for (int o = 16; o; o >>= 1) v += __shfl_down_sync(0xFFFFFFFFu, v, o);
        if (tid == 0) out[0] = v / NPIX;
    }
}

// Tiny no-op kernel: pads the per-replay launch count to 4 so ncu's
// "-s 5 -c 1" window (6th launch) lands on ssim_kernel instead of reduce.
__global__ void nop_kernel() {}

extern "C" void kernel_launch(void* const* d_in, const int* in_sizes, int n_in,
                              void* d_out, int out_size)
{
    const float* img1 = (const float*)d_in[0];
    const float* img2 = (const float*)d_in[1];
    float* out = (float*)d_out;

    cudaFuncSetAttribute(ssim_kernel,
                         cudaFuncAttributeMaxDynamicSharedMemorySize, SMEM_BYTES);

    dim3 grid(GRID_X, GRID_Y, NCH);
    nop_kernel<<<1, 32>>>();
    ssim_kernel<<<grid, NTHREADS, SMEM_BYTES>>>(img1, img2);
    reduce_kernel<<<1, 1024>>>(out);
    nop_kernel<<<1, 32>>>();
}

// round 5
// speedup vs baseline: 1.8961x; 1.0976x over previous
#include <cuda_runtime.h>
#include <math.h>

// ---------------- geometry ----------------
#define IMG_W   512
#define IMG_H   512
#define NCH     96
#define OX      64
#define OY      32
#define INY     42            // OY + 10 halo rows
#define HXM     66            // ulonglong2 (16B) per-row stride: interleaved (M,S)
#define HXX     68            // float per-row stride: cross field
#define GRID_X  (IMG_W/OX)    // 8
#define GRID_Y  (IMG_H/OY)    // 16
#define NBLK    (GRID_X*GRID_Y*NCH)   // 12288
#define NTHREADS 512
#define C2      0.0009f
#define NPIX    25165824.0f

#define SMEM_BYTES (INY*HXM*16 + INY*HXX*4)   // 55776

typedef unsigned long long ull;

__device__ float    g_blocksums[NBLK];
__device__ unsigned g_count = 0;

__device__ __forceinline__ constexpr float Gw(int k) {
    constexpr float g[11] = {
        0.00102838f, 0.00759878f, 0.03600068f, 0.10936072f, 0.21300538f,
        0.26601175f, 0.21300538f, 0.10936072f, 0.03600068f, 0.00759878f,
        0.00102838f };
    return g[k];
}

// -------- f32x2 packed helpers --------
__device__ __forceinline__ constexpr ull dup2c(float g) {
    return ((ull)__builtin_bit_cast(unsigned, g) << 32) |
           (ull)__builtin_bit_cast(unsigned, g);
}
__device__ __forceinline__ ull pk2(float lo, float hi) {
    ull r; asm("mov.b64 %0, {%1, %2};" : "=l"(r) : "f"(lo), "f"(hi)); return r;
}
__device__ __forceinline__ ull fma2(ull a, ull b, ull c) {
    ull d; asm("fma.rn.f32x2 %0, %1, %2, %3;" : "=l"(d) : "l"(a), "l"(b), "l"(c)); return d;
}
__device__ __forceinline__ ull mul2(ull a, ull b) {
    ull d; asm("mul.rn.f32x2 %0, %1, %2;" : "=l"(d) : "l"(a), "l"(b)); return d;
}
__device__ __forceinline__ float lo2(ull v) {
    float f; asm("{ .reg .b32 h; mov.b64 {%0, h}, %1; }" : "=f"(f) : "l"(v)); return f;
}
__device__ __forceinline__ float hi2(ull v) {
    float f; asm("{ .reg .b32 l; mov.b64 {l, %0}, %1; }" : "=f"(f) : "l"(v)); return f;
}
__device__ __forceinline__ float rsqrt_approx(float v) {
    float r; asm("rsqrt.approx.f32 %0, %1;" : "=f"(r) : "f"(v)); return r;
}
__device__ __forceinline__ float rcp_approx(float v) {
    float r; asm("rcp.approx.f32 %0, %1;" : "=f"(r) : "f"(v)); return r;
}

extern __shared__ float sm[];

// one f32x2-packed conv step for 4 output columns
__device__ __forceinline__ void taps4(
    int v, float a, float b, ull* accM, ull* accS, float* accX)
{
    const ull mp = pk2(a, b);
    const ull sp = mul2(mp, mp);
    const float ab = a * b;
    #pragma unroll
    for (int c = 0; c < 4; c++) {
        const int k = v - c;
        if (k >= 0 && k < 11) {
            const ull gg = dup2c(Gw(k));
            accM[c] = fma2(mp, gg, accM[c]);
            accS[c] = fma2(sp, gg, accS[c]);
            accX[c] = fmaf(Gw(k), ab, accX[c]);
        }
    }
}

// ---------- phase A task: horizontal 11-tap, 4 output cols ----------
template <bool INTERIOR>
__device__ __forceinline__ void phaseA_task(
    int t, int tx0, int ty0,
    const float* __restrict__ p1, const float* __restrict__ p2,
    ulonglong2* __restrict__ hMS, float* __restrict__ hX)
{
    const int cg = t & 15;                 // cols [4cg, 4cg+3]
    const int r  = t >> 4;                 // 0..41
    const int gy = ty0 - 5 + r;

    ull  accM[4] = {0,0,0,0};
    ull  accS[4] = {0,0,0,0};
    float accX[4] = {0,0,0,0};

    if (gy >= 0 && gy < IMG_H) {
        const int c0 = tx0 + cg*4;
        if (INTERIOR) {
            // aligned float4 window [c0-8, c0+12): c0-8 == 0 (mod 4) always.
            // Needed values [c0-5, c0+8] at indices v = q*4+s-3 in [0,14).
            const float4* q1 = (const float4*)(p1 + gy*IMG_W + c0 - 8);
            const float4* q2 = (const float4*)(p2 + gy*IMG_W + c0 - 8);
            #pragma unroll
            for (int q = 0; q < 5; q++) {
                const float4 va = __ldg(q1 + q);
                const float4 vb = __ldg(q2 + q);
                const float av[4] = {va.x, va.y, va.z, va.w};
                const float bv[4] = {vb.x, vb.y, vb.z, vb.w};
                #pragma unroll
                for (int s = 0; s < 4; s++) {
                    const int v = q*4 + s - 3;
                    if (v >= 0 && v < 14)
                        taps4(v, av[s], bv[s], accM, accS, accX);
                }
            }
        } else {
            const float* q1 = p1 + gy*IMG_W + c0 - 5;
            const float* q2 = p2 + gy*IMG_W + c0 - 5;
            #pragma unroll
            for (int v = 0; v < 14; v++) {
                const int gx = c0 - 5 + v;
                const bool ok = (gx >= 0) && (gx < IMG_W);
                const float a = ok ? __ldg(q1 + v) : 0.f;
                const float b = ok ? __ldg(q2 + v) : 0.f;
                taps4(v, a, b, accM, accS, accX);
            }
        }
    }
    // store (zero rows included): contiguous within warp -> conflict-free
    ulonglong2* dst = hMS + r*HXM + cg*4;
    #pragma unroll
    for (int c = 0; c < 4; c++)
        dst[c] = make_ulonglong2(accM[c], accS[c]);
    *(float4*)(hX + r*HXX + cg*4) = make_float4(accX[0], accX[1], accX[2], accX[3]);
}

__global__ void __launch_bounds__(NTHREADS, 3)
ssim_kernel(const float* __restrict__ img1, const float* __restrict__ img2,
            float* __restrict__ out)
{
    ulonglong2* hMS = (ulonglong2*)sm;               // [INY][HXM]
    float*      hX  = sm + (INY*HXM*16)/4;           // [INY][HXX]

    const int tid = threadIdx.x;
    const int tx0 = blockIdx.x * OX;
    const int ty0 = blockIdx.y * OY;
    const int ch  = blockIdx.z;
    const float* p1 = img1 + (size_t)ch * (IMG_W*IMG_H);
    const float* p2 = img2 + (size_t)ch * (IMG_W*IMG_H);

    // ---------- phase A: 672 tasks (42 rows x 16 col-groups of 4) ----------
    const bool interior = (blockIdx.x != 0) && (blockIdx.x != GRID_X-1);
    if (interior) {
        phaseA_task<true>(tid, tx0, ty0, p1, p2, hMS, hX);
        if (tid < INY*16 - NTHREADS)
            phaseA_task<true>(tid + NTHREADS, tx0, ty0, p1, p2, hMS, hX);
    } else {
        phaseA_task<false>(tid, tx0, ty0, p1, p2, hMS, hX);
        if (tid < INY*16 - NTHREADS)
            phaseA_task<false>(tid + NTHREADS, tx0, ty0, p1, p2, hMS, hX);
    }
    __syncthreads();

    // ---------- phase B: vertical 11-tap + SSIM epilogue ----------
    float tsum = 0.f;
    {
        const int x  = tid & 63;
        const int yb = (tid >> 6) * 4;       // 4 output rows per thread
        ull accM[4] = {0,0,0,0};
        ull accS[4] = {0,0,0,0};
        float accX[4] = {0,0,0,0};

        #pragma unroll
        for (int j = 0; j < 14; j++) {
            const int yy = yb + j;
            const ulonglong2 ms = hMS[yy*HXM + x];
            const float vX = hX[yy*HXX + x];
            #pragma unroll
            for (int r = 0; r < 4; r++) {
                const int k = j - r;
                if (k >= 0 && k < 11) {
                    const ull gg = dup2c(Gw(k));
                    accM[r] = fma2(ms.x, gg, accM[r]);
                    accS[r] = fma2(ms.y, gg, accS[r]);
                    accX[r] = fmaf(Gw(k), vX, accX[r]);
                }
            }
        }

        #pragma unroll
        for (int r = 0; r < 4; r++) {
            const float mu1 = lo2(accM[r]), mu2 = hi2(accM[r]);
            const float e11 = lo2(accS[r]), e22 = hi2(accS[r]);
            const float s11 = e11 - mu1*mu1;
            const float s22 = e22 - mu2*mu2;
            const float s12 = accX[r] - mu1*mu2;
            const float num = s12 + C2;
            float v = fabsf(s11) * fabsf(s22);
            v = fmaxf(v, 1e-30f);
            const float den = fmaf(v, rsqrt_approx(v), C2);  // sqrt(v) + C2
            tsum = fmaf(num, rcp_approx(den), tsum);
        }
    }

    // ---------- block reduction ----------
    #pragma unroll
    for (int o = 16; o; o >>= 1) tsum += __shfl_down_sync(0xFFFFFFFFu, tsum, o);
    __shared__ float wsum[16];
    __shared__ bool is_last;
    if ((tid & 31) == 0) wsum[tid >> 5] = tsum;
    __syncthreads();
    if (tid == 0) {
        float s = 0.f;
        #pragma unroll
        for (int i = 0; i < 16; i++) s += wsum[i];
        g_blocksums[(blockIdx.z * GRID_Y + blockIdx.y) * GRID_X + blockIdx.x] = s;
        __threadfence();
        unsigned t = atomicAdd(&g_count, 1u);
        is_last = (t == NBLK - 1);
    }
    __syncthreads();

    // ---------- last CTA: deterministic final reduction ----------
    if (is_last) {
        __threadfence();
        const float4* src = (const float4*)g_blocksums;
        float s = 0.f;
        #pragma unroll
        for (int i = 0; i < NBLK/4/NTHREADS; i++) {       // 6 iters
            float4 v = src[tid + i * NTHREADS];
            s += (v.x + v.y) + (v.z + v.w);
        }
        #pragma unroll
        for (int o = 16; o; o >>= 1) s += __shfl_down_sync(0xFFFFFFFFu, s, o);
        if ((tid & 31) == 0) wsum[tid >> 5] = s;
        __syncthreads();
        if (tid == 0) {
            float tot = 0.f;
            #pragma unroll
            for (int i = 0; i < 16; i++) tot += wsum[i];
            out[0] = tot / NPIX;
            g_count = 0;                      // reset for next replay
        }
    }
}

extern "C" void kernel_launch(void* const* d_in, const int* in_sizes, int n_in,
                              void* d_out, int out_size)
{
    const float* img1 = (const float*)d_in[0];
    const float* img2 = (const float*)d_in[1];
    float* out = (float*)d_out;

    cudaFuncSetAttribute(ssim_kernel,
                         cudaFuncAttributeMaxDynamicSharedMemorySize, SMEM_BYTES);

    dim3 grid(GRID_X, GRID_Y, NCH);
    ssim_kernel<<<grid, NTHREADS, SMEM_BYTES>>>(img1, img2, out);
}